// round 16
// baseline (speedup 1.0000x reference)
#include <cuda_runtime.h>
#include <cstdint>

#define NN 100000
#define NE 1600000
typedef unsigned long long ull;

// ---------------- scratch (device globals; allocation-free) ----------------
__device__ __align__(16) float  g_wperm[128 * 128];     // k-interleaved integer W
__device__ float g_wscale;                              // weight quant scale
__device__ __align__(16) float  g_vedge[2 * 32];        // folded edge attention vectors
__device__ __align__(16) float  g_xp[(size_t)NN * 128]; // projected nodes [N][128] fp32
__device__ __align__(16) float2 g_asrc[NN];
__device__ __align__(16) float2 g_adst[NN];
__device__ __align__(16) float2 g_aedge[NE];            // per-edge attn logits (ea . v)
__device__ __align__(16) int2   g_epack[NE];            // compact (src, dst)
__device__ __align__(16) float2 g_ex[NE];               // exp(alpha) per edge
__device__ __align__(16) float2 g_denom[NN];            // softmax denominators
__device__ __align__(16) float2 g_rden[NN];             // 0.5 / (denom + eps)
__device__ __align__(16) float  g_out[(size_t)NN * 64]; // head-mean accumulator
__device__ unsigned int g_maxabs;
__device__ int g_idx32;                                 // 1 if edge_index is int32

// ---------------- kernel: pack edge index to int2 (hidden on side stream) ---
__global__ void k_pack(const void* __restrict__ ei) {
    int e = blockIdx.x * 256 + threadIdx.x;
    if (e >= NE) return;
    int src, dst;
    if (g_idx32) {
        const int* p = (const int*)ei;
        src = p[e]; dst = p[NE + e];
    } else {
        const long long* p = (const long long*)ei;
        src = (int)p[e]; dst = (int)p[NE + e];
    }
    if ((unsigned)src >= NN) src = 0;
    if ((unsigned)dst >= NN) dst = 0;
    g_epack[e] = make_int2(src, dst);
}

// ---------------- kernel 1: probe + weight fake-quant + edge fold ----------
__global__ void k_prep(const void* __restrict__ ei,
                       const float* __restrict__ w_lin,
                       const float* __restrict__ w_edge,
                       const float* __restrict__ att_edge) {
    __shared__ float red[256];
    int t = threadIdx.x;
    if (t == 0) {   // index-width probe (int64 values in-range <=> int64 layout)
        const long long* p = (const long long*)ei;
        int bad = 0;
        for (int i = 0; i < 64; i++) {
            long long v = p[i];
            if (v < 0 || v >= NN) bad = 1;
        }
        g_idx32 = bad;
    }
    float m = 0.f;
    for (int i = t; i < 16384; i += 256) m = fmaxf(m, fabsf(w_lin[i]));
    red[t] = m;
    __syncthreads();
    for (int s = 128; s > 0; s >>= 1) {
        if (t < s) red[t] = fmaxf(red[t], red[t + s]);
        __syncthreads();
    }
    float scale = red[0] / 127.0f + 1e-12f;
    if (t == 0) g_wscale = scale;
    for (int i = t; i < 16384; i += 256) {
        float q = fminf(fmaxf(rintf(w_lin[i] / scale), -128.f), 127.f);
        int n = i >> 7, k = i & 127;
        int pos = (k & ~15) + ((k & 3) << 2) + ((k & 15) >> 2);
        g_wperm[(n << 7) + pos] = q;     // integer value, exact in tf32
    }
    if (t < 64) {
        int h = t >> 5, d = t & 31;
        float s = 0.f;
        for (int c = 0; c < 64; c++)
            s += w_edge[(h * 64 + c) * 32 + d] * att_edge[h * 64 + c];
        g_vedge[t] = s;
    }
}

// ---------------- kernel 2: projection via tf32 MMA, warp tile m16n64 ------
// 256-thread blocks (64 rows/block): 3 blocks/SM -> 24 resident warps.
#define WS 144          // W smem row stride (floats): conflict-free LDS.128
#define PROJ_SMEM ((128 * WS + 256) * 4)

__device__ __forceinline__ uint32_t f2tf32(float f) {
    uint32_t u;
    asm("cvt.rna.tf32.f32 %0, %1;" : "=r"(u) : "f"(f));
    return u;
}

__global__ __launch_bounds__(256) void k_projmma(const float* __restrict__ x,
                                                 const float* __restrict__ att_src,
                                                 const float* __restrict__ att_dst) {
    extern __shared__ float sm[];
    float* sw   = sm;                   // W 128 x WS (k-interleaved)
    float* s_as = sm + 128 * WS;
    float* s_ad = s_as + 128;

    int tid = threadIdx.x;
    int base = blockIdx.x * 64;

    if (tid < 128) { s_as[tid] = att_src[tid]; s_ad[tid] = att_dst[tid]; }

    for (int i = tid; i < 4096; i += 256) {
        int n = i >> 5, c = i & 31;
        *(float4*)&sw[n * WS + c * 4] = ((const float4*)g_wperm)[i];
    }
    __syncthreads();

    int warp = tid >> 5, lane = tid & 31;
    int wm = warp >> 1, wn = warp & 1;       // 4 m-groups x 2 n-halves
    int g = lane >> 2, t = lane & 3;
    int mrow = wm * 16;

    int row0 = base + mrow + g;
    int row1 = row0 + 8;
    int r0c = row0 < NN ? row0 : NN - 1;
    int r1c = row1 < NN ? row1 : NN - 1;
    const float* xr0 = x + (size_t)r0c * 128;
    const float* xr1 = x + (size_t)r1c * 128;

    float acc[32];
#pragma unroll
    for (int i = 0; i < 32; i++) acc[i] = 0.f;

    float xa[8];
#pragma unroll
    for (int j = 0; j < 4; j++) {
        xa[2 * j]     = xr0[t + 4 * j];
        xa[2 * j + 1] = xr1[t + 4 * j];
    }

    for (int ktp = 0; ktp < 8; ktp++) {
        float xb[8];
        if (ktp < 7) {
            int k0 = (ktp + 1) * 16;
#pragma unroll
            for (int j = 0; j < 4; j++) {
                xb[2 * j]     = xr0[k0 + t + 4 * j];
                xb[2 * j + 1] = xr1[k0 + t + 4 * j];
            }
        }
        uint32_t ah[8], al[8];
#pragma unroll
        for (int i = 0; i < 8; i++) {
            ah[i] = f2tf32(xa[i]);
            al[i] = f2tf32(xa[i] - __uint_as_float(ah[i]));
        }
        int swoff = ktp * 16 + t * 4;
#pragma unroll
        for (int nti = 0; nti < 8; nti++) {
            int nt = wn * 8 + nti;
            float4 b = *(const float4*)&sw[(nt * 8 + g) * WS + swoff];
            uint32_t b0 = __float_as_uint(b.x);
            uint32_t b1 = __float_as_uint(b.y);
            uint32_t b2 = __float_as_uint(b.z);
            uint32_t b3 = __float_as_uint(b.w);
            float* c4 = &acc[nti * 4];
            asm("mma.sync.aligned.m16n8k8.row.col.f32.tf32.tf32.f32 "
                "{%0,%1,%2,%3}, {%4,%5,%6,%7}, {%8,%9}, {%0,%1,%2,%3};"
                : "+f"(c4[0]), "+f"(c4[1]), "+f"(c4[2]), "+f"(c4[3])
                : "r"(ah[0]), "r"(ah[1]), "r"(ah[2]), "r"(ah[3]), "r"(b0), "r"(b1));
            asm("mma.sync.aligned.m16n8k8.row.col.f32.tf32.tf32.f32 "
                "{%0,%1,%2,%3}, {%4,%5,%6,%7}, {%8,%9}, {%0,%1,%2,%3};"
                : "+f"(c4[0]), "+f"(c4[1]), "+f"(c4[2]), "+f"(c4[3])
                : "r"(al[0]), "r"(al[1]), "r"(al[2]), "r"(al[3]), "r"(b0), "r"(b1));
            asm("mma.sync.aligned.m16n8k8.row.col.f32.tf32.tf32.f32 "
                "{%0,%1,%2,%3}, {%4,%5,%6,%7}, {%8,%9}, {%0,%1,%2,%3};"
                : "+f"(c4[0]), "+f"(c4[1]), "+f"(c4[2]), "+f"(c4[3])
                : "r"(ah[4]), "r"(ah[5]), "r"(ah[6]), "r"(ah[7]), "r"(b2), "r"(b3));
            asm("mma.sync.aligned.m16n8k8.row.col.f32.tf32.tf32.f32 "
                "{%0,%1,%2,%3}, {%4,%5,%6,%7}, {%8,%9}, {%0,%1,%2,%3};"
                : "+f"(c4[0]), "+f"(c4[1]), "+f"(c4[2]), "+f"(c4[3])
                : "r"(al[4]), "r"(al[5]), "r"(al[6]), "r"(al[7]), "r"(b2), "r"(b3));
        }
#pragma unroll
        for (int i = 0; i < 8; i++) xa[i] = xb[i];
    }

    // epilogue: scale, store xp (fp32), fold this warp's head logits
    float scale = g_wscale;
    float as_r0 = 0.f, ad_r0 = 0.f, as_r1 = 0.f, ad_r1 = 0.f;

#pragma unroll
    for (int nti = 0; nti < 8; nti++) {
        int c = (wn * 8 + nti) * 8 + 2 * t;
        float y0 = acc[nti * 4 + 0] * scale;
        float y1 = acc[nti * 4 + 1] * scale;
        float y2 = acc[nti * 4 + 2] * scale;
        float y3 = acc[nti * 4 + 3] * scale;
        if (row0 < NN) *(float2*)&g_xp[(size_t)row0 * 128 + c] = make_float2(y0, y1);
        if (row1 < NN) *(float2*)&g_xp[(size_t)row1 * 128 + c] = make_float2(y2, y3);
        float sa = s_as[c], sa1 = s_as[c + 1];
        float da = s_ad[c], da1 = s_ad[c + 1];
        as_r0 += y0 * sa + y1 * sa1;  ad_r0 += y0 * da + y1 * da1;
        as_r1 += y2 * sa + y3 * sa1;  ad_r1 += y2 * da + y3 * da1;
    }
#pragma unroll
    for (int s = 1; s <= 2; s <<= 1) {
        as_r0 += __shfl_xor_sync(~0u, as_r0, s);
        ad_r0 += __shfl_xor_sync(~0u, ad_r0, s);
        as_r1 += __shfl_xor_sync(~0u, as_r1, s);
        ad_r1 += __shfl_xor_sync(~0u, ad_r1, s);
    }
    if (t == 0) {
        if (row0 < NN) {
            ((float*)&g_asrc[row0])[wn] = as_r0;
            ((float*)&g_adst[row0])[wn] = ad_r0;
        }
        if (row1 < NN) {
            ((float*)&g_asrc[row1])[wn] = as_r1;
            ((float*)&g_adst[row1])[wn] = ad_r1;
        }
    }
}

// ---------------- kernel 3a: edge-attr logits, smem-staged coalesced -------
// 256 edges per block; ea tile staged via fully-coalesced float4 loads.
__global__ __launch_bounds__(256) void k_edgeA(const float* __restrict__ ea) {
    __shared__ float4 sea[256 * 9];      // stride 9 float4 -> conflict-free reads
    int tid = threadIdx.x;
    int base = blockIdx.x * 256;         // NE % 256 == 0
    const float4* src = (const float4*)ea + (size_t)base * 8;
    for (int i = tid; i < 2048; i += 256) {
        int e = i >> 3, j = i & 7;
        sea[e * 9 + j] = src[i];
    }
    __syncthreads();

    const float4* eap = &sea[tid * 9];
    const float4* v4 = (const float4*)g_vedge;
    float a0 = 0.f, a1 = 0.f;
#pragma unroll
    for (int j = 0; j < 8; j++) {
        float4 t = eap[j];
        float4 v0 = v4[j], v1 = v4[8 + j];
        a0 += t.x * v0.x + t.y * v0.y + t.z * v0.z + t.w * v0.w;
        a1 += t.x * v1.x + t.y * v1.y + t.z * v1.z + t.w * v1.w;
    }
    g_aedge[base + tid] = make_float2(a0, a1);
}

// ---------------- kernel 3b: logits combine, exp, denominators -------------
__global__ void k_edgeB() {
    int e = blockIdx.x * 256 + threadIdx.x;
    if (e >= NE) return;
    int2 sd = __ldcs(&g_epack[e]);            // streamed: one-time read
    float2 aeg = __ldcs(&g_aedge[e]);
    float2 as = g_asrc[sd.x];
    float2 ad = g_adst[sd.y];
    float al0 = as.x + ad.x + aeg.x;
    float al1 = as.y + ad.y + aeg.y;
    al0 = al0 >= 0.f ? al0 : 0.2f * al0;      // leaky relu
    al1 = al1 >= 0.f ? al1 : 0.2f * al1;
    float e0 = __expf(al0), e1 = __expf(al1); // |alpha| O(10): exp safe; MUFU ok
    g_ex[e] = make_float2(e0, e1);
    atomicAdd(&g_denom[sd.y], make_float2(e0, e1));   // sm_90+ vector red
}

// ---------------- kernel 3c: reciprocal denominators ----------------------
__global__ void k_inv() {
    int i = blockIdx.x * 256 + threadIdx.x;
    if (i >= NN) return;
    float2 d = g_denom[i];
    g_rden[i] = make_float2(0.5f / (d.x + 1e-16f), 0.5f / (d.y + 1e-16f));
}

// ---------------- kernel 4: weighted message scatter (16 lanes / edge) -----
__global__ void k_scatter() {
    int gw = (blockIdx.x * 256 + threadIdx.x) >> 5;   // global warp id
    int lane = threadIdx.x & 31;
    int half = lane >> 4, sub = lane & 15;
    long long e = (long long)gw * 2 + half;
    if (e >= NE) return;
    int2 sd = __ldcs(&g_epack[e]);                     // streamed
    float2 ex = __ldcs(&g_ex[e]);                      // streamed
    float2 rd = g_rden[sd.y];
    float c0 = ex.x * rd.x;                            // 0.5/denom folded
    float c1 = ex.y * rd.y;
    const float4* xr = (const float4*)(g_xp + (size_t)sd.x * 128);
    float4 a = xr[sub];        // head 0, channels 4*sub..4*sub+3
    float4 b = xr[16 + sub];   // head 1, same channels
    float4 m = make_float4(a.x * c0 + b.x * c1, a.y * c0 + b.y * c1,
                           a.z * c0 + b.z * c1, a.w * c0 + b.w * c1);
    atomicAdd((float4*)(g_out + (size_t)sd.y * 64 + sub * 4), m);  // vector red
}

// ---------------- kernel 5: global abs-max of (out + bias) ----------------
__global__ void k_max(const float* __restrict__ bias) {
    __shared__ float red[8];
    float m = 0.f;
    for (int i = blockIdx.x * 256 + threadIdx.x; i < 1600000; i += gridDim.x * 256) {
        float4 v = ((const float4*)g_out)[i];
        int c = (i * 4) & 63;
        v.x += bias[c]; v.y += bias[c + 1]; v.z += bias[c + 2]; v.w += bias[c + 3];
        m = fmaxf(m, fmaxf(fmaxf(fabsf(v.x), fabsf(v.y)), fmaxf(fabsf(v.z), fabsf(v.w))));
    }
#pragma unroll
    for (int s = 16; s; s >>= 1) m = fmaxf(m, __shfl_xor_sync(~0u, m, s));
    if ((threadIdx.x & 31) == 0) red[threadIdx.x >> 5] = m;
    __syncthreads();
    if (threadIdx.x == 0) {
        for (int w = 1; w < 8; w++) m = fmaxf(m, red[w]);
        atomicMax(&g_maxabs, __float_as_uint(m));
    }
}

// ---------------- kernel 6: output fake-quant + store ----------------
__global__ void k_quant(const float* __restrict__ bias, float* __restrict__ out) {
    int i = blockIdx.x * 256 + threadIdx.x;
    if (i >= 1600000) return;
    float scale = __uint_as_float(g_maxabs) / 127.0f + 1e-12f;
    float4 v = ((const float4*)g_out)[i];
    int c = (i * 4) & 63;
    v.x += bias[c]; v.y += bias[c + 1]; v.z += bias[c + 2]; v.w += bias[c + 3];
    float4 q;
    q.x = fminf(fmaxf(rintf(v.x / scale), -128.f), 127.f) * scale;
    q.y = fminf(fmaxf(rintf(v.y / scale), -128.f), 127.f) * scale;
    q.z = fminf(fmaxf(rintf(v.z / scale), -128.f), 127.f) * scale;
    q.w = fminf(fmaxf(rintf(v.w / scale), -128.f), 127.f) * scale;
    ((float4*)out)[i] = q;
}

// ---------------- launch ----------------
extern "C" void kernel_launch(void* const* d_in, const int* in_sizes, int n_in,
                              void* d_out, int out_size) {
    const float* x        = (const float*)d_in[0];
    const void*  ei       = d_in[1];
    const float* ea       = (const float*)d_in[2];
    const float* w_lin    = (const float*)d_in[3];
    const float* w_edge   = (const float*)d_in[4];
    const float* att_src  = (const float*)d_in[5];
    const float* att_dst  = (const float*)d_in[6];
    const float* att_edge = (const float*)d_in[7];
    const float* bias     = (const float*)d_in[8];
    float*       out      = (float*)d_out;

    static cudaStream_t s1 = nullptr, s2 = nullptr;
    static cudaEvent_t evF = nullptr, evJ1 = nullptr, evJ2 = nullptr;
    static void *p_out = nullptr, *p_denom = nullptr, *p_maxabs = nullptr;
    if (!s1) {   // one-time setup (host objects only; first call is uncaptured)
        cudaStreamCreateWithFlags(&s1, cudaStreamNonBlocking);
        cudaStreamCreateWithFlags(&s2, cudaStreamNonBlocking);
        cudaEventCreateWithFlags(&evF, cudaEventDisableTiming);
        cudaEventCreateWithFlags(&evJ1, cudaEventDisableTiming);
        cudaEventCreateWithFlags(&evJ2, cudaEventDisableTiming);
        cudaGetSymbolAddress(&p_out, g_out);
        cudaGetSymbolAddress(&p_denom, g_denom);
        cudaGetSymbolAddress(&p_maxabs, g_maxabs);
        cudaFuncSetAttribute(k_projmma, cudaFuncAttributeMaxDynamicSharedMemorySize,
                             PROJ_SMEM);
    }

    k_prep<<<1, 256>>>(ei, w_lin, w_edge, att_edge);

    // fork: s1 = edgeA (DRAM-bound); s2 = memsets + edge packing
    cudaEventRecord(evF, 0);
    cudaStreamWaitEvent(s1, evF, 0);
    cudaStreamWaitEvent(s2, evF, 0);
    k_edgeA<<<NE / 256, 256, 0, s1>>>(ea);
    cudaMemsetAsync(p_out, 0, (size_t)NN * 64 * sizeof(float), s2);
    cudaMemsetAsync(p_denom, 0, (size_t)NN * sizeof(float2), s2);
    cudaMemsetAsync(p_maxabs, 0, sizeof(unsigned int), s2);
    k_pack<<<(NE + 255) / 256, 256, 0, s2>>>(ei);

    k_projmma<<<(NN + 63) / 64, 256, PROJ_SMEM>>>(x, att_src, att_dst);

    // join both side streams
    cudaEventRecord(evJ1, s1);
    cudaEventRecord(evJ2, s2);
    cudaStreamWaitEvent(0, evJ1, 0);
    cudaStreamWaitEvent(0, evJ2, 0);

    k_edgeB<<<(NE + 255) / 256, 256>>>();
    k_inv<<<(NN + 255) / 256, 256>>>();
    k_scatter<<<(NE / 2 * 32 + 255) / 256, 256>>>();   // 16 lanes per edge
    k_max<<<1024, 256>>>(bias);
    k_quant<<<6250, 256>>>(bias, out);
}

// round 17
// speedup vs baseline: 1.0213x; 1.0213x over previous
#include <cuda_runtime.h>
#include <cstdint>

#define NN 100000
#define NE 1600000
typedef unsigned long long ull;

// ---------------- scratch (device globals; allocation-free) ----------------
__device__ __align__(16) float  g_wperm[128 * 128];     // k-interleaved integer W
__device__ float g_wscale;                              // weight quant scale
__device__ __align__(16) float  g_vedge[2 * 32];        // folded edge attention vectors
__device__ __align__(16) float  g_xp[(size_t)NN * 128]; // projected nodes [N][128] fp32
__device__ __align__(16) float2 g_asrc[NN];
__device__ __align__(16) float2 g_adst[NN];
__device__ __align__(16) float2 g_aedge[NE];            // per-edge attn logits (ea . v)
__device__ __align__(16) int2   g_epack[NE];            // compact (src, dst)
__device__ __align__(16) float2 g_ex[NE];               // exp(alpha) per edge
__device__ __align__(16) float2 g_denom[NN];            // softmax denominators
__device__ __align__(16) float2 g_rden[NN];             // 0.5 / (denom + eps)
__device__ __align__(16) float  g_out[(size_t)NN * 64]; // head-mean accumulator
__device__ unsigned int g_maxabs;
__device__ int g_idx32;                                 // 1 if edge_index is int32

// ---------------- kernel: pack edge index to int2 (hidden on side stream) ---
__global__ void k_pack(const void* __restrict__ ei) {
    int e = blockIdx.x * 256 + threadIdx.x;
    if (e >= NE) return;
    int src, dst;
    if (g_idx32) {
        const int* p = (const int*)ei;
        src = p[e]; dst = p[NE + e];
    } else {
        const long long* p = (const long long*)ei;
        src = (int)p[e]; dst = (int)p[NE + e];
    }
    if ((unsigned)src >= NN) src = 0;
    if ((unsigned)dst >= NN) dst = 0;
    g_epack[e] = make_int2(src, dst);
}

// ---------------- kernel 1: probe + weight fake-quant + edge fold ----------
__global__ void k_prep(const void* __restrict__ ei,
                       const float* __restrict__ w_lin,
                       const float* __restrict__ w_edge,
                       const float* __restrict__ att_edge) {
    __shared__ float red[256];
    int t = threadIdx.x;
    if (t == 0) {   // index-width probe (int64 values in-range <=> int64 layout)
        const long long* p = (const long long*)ei;
        int bad = 0;
        for (int i = 0; i < 64; i++) {
            long long v = p[i];
            if (v < 0 || v >= NN) bad = 1;
        }
        g_idx32 = bad;
    }
    float m = 0.f;
    for (int i = t; i < 16384; i += 256) m = fmaxf(m, fabsf(w_lin[i]));
    red[t] = m;
    __syncthreads();
    for (int s = 128; s > 0; s >>= 1) {
        if (t < s) red[t] = fmaxf(red[t], red[t + s]);
        __syncthreads();
    }
    float scale = red[0] / 127.0f + 1e-12f;
    if (t == 0) g_wscale = scale;
    for (int i = t; i < 16384; i += 256) {
        float q = fminf(fmaxf(rintf(w_lin[i] / scale), -128.f), 127.f);
        int n = i >> 7, k = i & 127;
        int pos = (k & ~15) + ((k & 3) << 2) + ((k & 15) >> 2);
        g_wperm[(n << 7) + pos] = q;     // integer value, exact in tf32
    }
    if (t < 64) {
        int h = t >> 5, d = t & 31;
        float s = 0.f;
        for (int c = 0; c < 64; c++)
            s += w_edge[(h * 64 + c) * 32 + d] * att_edge[h * 64 + c];
        g_vedge[t] = s;
    }
}

// ---------------- kernel 2: projection via tf32 MMA, warp tile m16n64 ------
// 512 threads, 128 rows/block (validated best: 67us)
#define WS 144          // W smem row stride (floats)
#define PROJ_SMEM ((128 * WS + 256) * 4)

__device__ __forceinline__ uint32_t f2tf32(float f) {
    uint32_t u;
    asm("cvt.rna.tf32.f32 %0, %1;" : "=r"(u) : "f"(f));
    return u;
}

__global__ __launch_bounds__(512) void k_projmma(const float* __restrict__ x,
                                                 const float* __restrict__ att_src,
                                                 const float* __restrict__ att_dst) {
    extern __shared__ float sm[];
    float* sw   = sm;                   // W 128 x WS (k-interleaved)
    float* s_as = sm + 128 * WS;
    float* s_ad = s_as + 128;

    int tid = threadIdx.x;
    int base = blockIdx.x * 128;

    if (tid < 128) { s_as[tid] = att_src[tid]; s_ad[tid] = att_dst[tid]; }

    for (int i = tid; i < 4096; i += 512) {
        int n = i >> 5, c = i & 31;
        *(float4*)&sw[n * WS + c * 4] = ((const float4*)g_wperm)[i];
    }
    __syncthreads();

    int warp = tid >> 5, lane = tid & 31;
    int wm = warp >> 1, wn = warp & 1;
    int g = lane >> 2, t = lane & 3;
    int mrow = wm * 16;

    int row0 = base + mrow + g;
    int row1 = row0 + 8;
    int r0c = row0 < NN ? row0 : NN - 1;
    int r1c = row1 < NN ? row1 : NN - 1;
    const float* xr0 = x + (size_t)r0c * 128;
    const float* xr1 = x + (size_t)r1c * 128;

    float acc[32];
#pragma unroll
    for (int i = 0; i < 32; i++) acc[i] = 0.f;

    float xa[8];
#pragma unroll
    for (int j = 0; j < 4; j++) {
        xa[2 * j]     = xr0[t + 4 * j];
        xa[2 * j + 1] = xr1[t + 4 * j];
    }

    for (int ktp = 0; ktp < 8; ktp++) {
        float xb[8];
        if (ktp < 7) {
            int k0 = (ktp + 1) * 16;
#pragma unroll
            for (int j = 0; j < 4; j++) {
                xb[2 * j]     = xr0[k0 + t + 4 * j];
                xb[2 * j + 1] = xr1[k0 + t + 4 * j];
            }
        }
        uint32_t ah[8], al[8];
#pragma unroll
        for (int i = 0; i < 8; i++) {
            ah[i] = f2tf32(xa[i]);
            al[i] = f2tf32(xa[i] - __uint_as_float(ah[i]));
        }
        int swoff = ktp * 16 + t * 4;
#pragma unroll
        for (int nti = 0; nti < 8; nti++) {
            int nt = wn * 8 + nti;
            float4 b = *(const float4*)&sw[(nt * 8 + g) * WS + swoff];
            uint32_t b0 = __float_as_uint(b.x);
            uint32_t b1 = __float_as_uint(b.y);
            uint32_t b2 = __float_as_uint(b.z);
            uint32_t b3 = __float_as_uint(b.w);
            float* c4 = &acc[nti * 4];
            asm("mma.sync.aligned.m16n8k8.row.col.f32.tf32.tf32.f32 "
                "{%0,%1,%2,%3}, {%4,%5,%6,%7}, {%8,%9}, {%0,%1,%2,%3};"
                : "+f"(c4[0]), "+f"(c4[1]), "+f"(c4[2]), "+f"(c4[3])
                : "r"(ah[0]), "r"(ah[1]), "r"(ah[2]), "r"(ah[3]), "r"(b0), "r"(b1));
            asm("mma.sync.aligned.m16n8k8.row.col.f32.tf32.tf32.f32 "
                "{%0,%1,%2,%3}, {%4,%5,%6,%7}, {%8,%9}, {%0,%1,%2,%3};"
                : "+f"(c4[0]), "+f"(c4[1]), "+f"(c4[2]), "+f"(c4[3])
                : "r"(al[0]), "r"(al[1]), "r"(al[2]), "r"(al[3]), "r"(b0), "r"(b1));
            asm("mma.sync.aligned.m16n8k8.row.col.f32.tf32.tf32.f32 "
                "{%0,%1,%2,%3}, {%4,%5,%6,%7}, {%8,%9}, {%0,%1,%2,%3};"
                : "+f"(c4[0]), "+f"(c4[1]), "+f"(c4[2]), "+f"(c4[3])
                : "r"(ah[4]), "r"(ah[5]), "r"(ah[6]), "r"(ah[7]), "r"(b2), "r"(b3));
            asm("mma.sync.aligned.m16n8k8.row.col.f32.tf32.tf32.f32 "
                "{%0,%1,%2,%3}, {%4,%5,%6,%7}, {%8,%9}, {%0,%1,%2,%3};"
                : "+f"(c4[0]), "+f"(c4[1]), "+f"(c4[2]), "+f"(c4[3])
                : "r"(al[4]), "r"(al[5]), "r"(al[6]), "r"(al[7]), "r"(b2), "r"(b3));
        }
#pragma unroll
        for (int i = 0; i < 8; i++) xa[i] = xb[i];
    }

    // epilogue: scale, store xp (fp32), fold this warp's head logits
    float scale = g_wscale;
    float as_r0 = 0.f, ad_r0 = 0.f, as_r1 = 0.f, ad_r1 = 0.f;

#pragma unroll
    for (int nti = 0; nti < 8; nti++) {
        int c = (wn * 8 + nti) * 8 + 2 * t;
        float y0 = acc[nti * 4 + 0] * scale;
        float y1 = acc[nti * 4 + 1] * scale;
        float y2 = acc[nti * 4 + 2] * scale;
        float y3 = acc[nti * 4 + 3] * scale;
        if (row0 < NN) *(float2*)&g_xp[(size_t)row0 * 128 + c] = make_float2(y0, y1);
        if (row1 < NN) *(float2*)&g_xp[(size_t)row1 * 128 + c] = make_float2(y2, y3);
        float sa = s_as[c], sa1 = s_as[c + 1];
        float da = s_ad[c], da1 = s_ad[c + 1];
        as_r0 += y0 * sa + y1 * sa1;  ad_r0 += y0 * da + y1 * da1;
        as_r1 += y2 * sa + y3 * sa1;  ad_r1 += y2 * da + y3 * da1;
    }
#pragma unroll
    for (int s = 1; s <= 2; s <<= 1) {
        as_r0 += __shfl_xor_sync(~0u, as_r0, s);
        ad_r0 += __shfl_xor_sync(~0u, ad_r0, s);
        as_r1 += __shfl_xor_sync(~0u, as_r1, s);
        ad_r1 += __shfl_xor_sync(~0u, ad_r1, s);
    }
    if (t == 0) {
        if (row0 < NN) {
            ((float*)&g_asrc[row0])[wn] = as_r0;
            ((float*)&g_adst[row0])[wn] = ad_r0;
        }
        if (row1 < NN) {
            ((float*)&g_asrc[row1])[wn] = as_r1;
            ((float*)&g_adst[row1])[wn] = ad_r1;
        }
    }
}

// ---------------- kernel 3a: edge-attr logits, smem-staged coalesced -------
__global__ __launch_bounds__(256) void k_edgeA(const float* __restrict__ ea) {
    __shared__ float4 sea[256 * 9];      // stride 9 float4 -> conflict-free reads
    int tid = threadIdx.x;
    int base = blockIdx.x * 256;         // NE % 256 == 0
    const float4* src = (const float4*)ea + (size_t)base * 8;
    for (int i = tid; i < 2048; i += 256) {
        int e = i >> 3, j = i & 7;
        sea[e * 9 + j] = src[i];
    }
    __syncthreads();

    const float4* eap = &sea[tid * 9];
    const float4* v4 = (const float4*)g_vedge;
    float a0 = 0.f, a1 = 0.f;
#pragma unroll
    for (int j = 0; j < 8; j++) {
        float4 t = eap[j];
        float4 v0 = v4[j], v1 = v4[8 + j];
        a0 += t.x * v0.x + t.y * v0.y + t.z * v0.z + t.w * v0.w;
        a1 += t.x * v1.x + t.y * v1.y + t.z * v1.z + t.w * v1.w;
    }
    g_aedge[base + tid] = make_float2(a0, a1);
}

// ---------------- kernel 3b: logits combine, exp, denominators -------------
__global__ void k_edgeB() {
    int e = blockIdx.x * 256 + threadIdx.x;
    if (e >= NE) return;
    int2 sd = __ldcs(&g_epack[e]);            // streamed: one-time read
    float2 aeg = __ldcs(&g_aedge[e]);
    float2 as = g_asrc[sd.x];
    float2 ad = g_adst[sd.y];
    float al0 = as.x + ad.x + aeg.x;
    float al1 = as.y + ad.y + aeg.y;
    al0 = al0 >= 0.f ? al0 : 0.2f * al0;      // leaky relu
    al1 = al1 >= 0.f ? al1 : 0.2f * al1;
    float e0 = __expf(al0), e1 = __expf(al1); // |alpha| O(10): exp safe; MUFU ok
    g_ex[e] = make_float2(e0, e1);
    atomicAdd(&g_denom[sd.y], make_float2(e0, e1));   // sm_90+ vector red
}

// ---------------- kernel 3c: reciprocal denominators ----------------------
__global__ void k_inv() {
    int i = blockIdx.x * 256 + threadIdx.x;
    if (i >= NN) return;
    float2 d = g_denom[i];
    g_rden[i] = make_float2(0.5f / (d.x + 1e-16f), 0.5f / (d.y + 1e-16f));
}

// ---------------- kernel 4: weighted message scatter (16 lanes / edge) -----
__global__ void k_scatter() {
    int gw = (blockIdx.x * 256 + threadIdx.x) >> 5;   // global warp id
    int lane = threadIdx.x & 31;
    int half = lane >> 4, sub = lane & 15;
    long long e = (long long)gw * 2 + half;
    if (e >= NE) return;
    int2 sd = __ldcs(&g_epack[e]);                     // streamed
    float2 ex = __ldcs(&g_ex[e]);                      // streamed
    float2 rd = g_rden[sd.y];
    float c0 = ex.x * rd.x;                            // 0.5/denom folded
    float c1 = ex.y * rd.y;
    const float4* xr = (const float4*)(g_xp + (size_t)sd.x * 128);
    float4 a = xr[sub];        // head 0, channels 4*sub..4*sub+3
    float4 b = xr[16 + sub];   // head 1, same channels
    float4 m = make_float4(a.x * c0 + b.x * c1, a.y * c0 + b.y * c1,
                           a.z * c0 + b.z * c1, a.w * c0 + b.w * c1);
    atomicAdd((float4*)(g_out + (size_t)sd.y * 64 + sub * 4), m);  // vector red
}

// ---------------- kernel 5: global abs-max of (out + bias) ----------------
__global__ void k_max(const float* __restrict__ bias) {
    __shared__ float red[8];
    float m = 0.f;
    for (int i = blockIdx.x * 256 + threadIdx.x; i < 1600000; i += gridDim.x * 256) {
        float4 v = ((const float4*)g_out)[i];
        int c = (i * 4) & 63;
        v.x += bias[c]; v.y += bias[c + 1]; v.z += bias[c + 2]; v.w += bias[c + 3];
        m = fmaxf(m, fmaxf(fmaxf(fabsf(v.x), fabsf(v.y)), fmaxf(fabsf(v.z), fabsf(v.w))));
    }
#pragma unroll
    for (int s = 16; s; s >>= 1) m = fmaxf(m, __shfl_xor_sync(~0u, m, s));
    if ((threadIdx.x & 31) == 0) red[threadIdx.x >> 5] = m;
    __syncthreads();
    if (threadIdx.x == 0) {
        for (int w = 1; w < 8; w++) m = fmaxf(m, red[w]);
        atomicMax(&g_maxabs, __float_as_uint(m));
    }
}

// ---------------- kernel 6: output fake-quant + store ----------------
__global__ void k_quant(const float* __restrict__ bias, float* __restrict__ out) {
    int i = blockIdx.x * 256 + threadIdx.x;
    if (i >= 1600000) return;
    float scale = __uint_as_float(g_maxabs) / 127.0f + 1e-12f;
    float4 v = ((const float4*)g_out)[i];
    int c = (i * 4) & 63;
    v.x += bias[c]; v.y += bias[c + 1]; v.z += bias[c + 2]; v.w += bias[c + 3];
    float4 q;
    q.x = fminf(fmaxf(rintf(v.x / scale), -128.f), 127.f) * scale;
    q.y = fminf(fmaxf(rintf(v.y / scale), -128.f), 127.f) * scale;
    q.z = fminf(fmaxf(rintf(v.z / scale), -128.f), 127.f) * scale;
    q.w = fminf(fmaxf(rintf(v.w / scale), -128.f), 127.f) * scale;
    ((float4*)out)[i] = q;
}

// ---------------- launch ----------------
extern "C" void kernel_launch(void* const* d_in, const int* in_sizes, int n_in,
                              void* d_out, int out_size) {
    const float* x        = (const float*)d_in[0];
    const void*  ei       = d_in[1];
    const float* ea       = (const float*)d_in[2];
    const float* w_lin    = (const float*)d_in[3];
    const float* w_edge   = (const float*)d_in[4];
    const float* att_src  = (const float*)d_in[5];
    const float* att_dst  = (const float*)d_in[6];
    const float* att_edge = (const float*)d_in[7];
    const float* bias     = (const float*)d_in[8];
    float*       out      = (float*)d_out;

    static cudaStream_t s1 = nullptr, s2 = nullptr;
    static cudaEvent_t evF = nullptr, evJ1 = nullptr, evJ2 = nullptr;
    static void *p_out = nullptr, *p_denom = nullptr, *p_maxabs = nullptr;
    if (!s1) {   // one-time setup (host objects only; first call is uncaptured)
        cudaStreamCreateWithFlags(&s1, cudaStreamNonBlocking);
        cudaStreamCreateWithFlags(&s2, cudaStreamNonBlocking);
        cudaEventCreateWithFlags(&evF, cudaEventDisableTiming);
        cudaEventCreateWithFlags(&evJ1, cudaEventDisableTiming);
        cudaEventCreateWithFlags(&evJ2, cudaEventDisableTiming);
        cudaGetSymbolAddress(&p_out, g_out);
        cudaGetSymbolAddress(&p_denom, g_denom);
        cudaGetSymbolAddress(&p_maxabs, g_maxabs);
        cudaFuncSetAttribute(k_projmma, cudaFuncAttributeMaxDynamicSharedMemorySize,
                             PROJ_SMEM);
    }

    k_prep<<<1, 256>>>(ei, w_lin, w_edge, att_edge);

    // fork: s1 = edgeA (coalesced); s2 = memsets + edge packing
    cudaEventRecord(evF, 0);
    cudaStreamWaitEvent(s1, evF, 0);
    cudaStreamWaitEvent(s2, evF, 0);
    k_edgeA<<<NE / 256, 256, 0, s1>>>(ea);
    cudaMemsetAsync(p_out, 0, (size_t)NN * 64 * sizeof(float), s2);
    cudaMemsetAsync(p_denom, 0, (size_t)NN * sizeof(float2), s2);
    cudaMemsetAsync(p_maxabs, 0, sizeof(unsigned int), s2);
    k_pack<<<(NE + 255) / 256, 256, 0, s2>>>(ei);

    k_projmma<<<(NN + 127) / 128, 512, PROJ_SMEM>>>(x, att_src, att_dst);

    // join both side streams
    cudaEventRecord(evJ1, s1);
    cudaEventRecord(evJ2, s2);
    cudaStreamWaitEvent(0, evJ1, 0);
    cudaStreamWaitEvent(0, evJ2, 0);

    k_edgeB<<<(NE + 255) / 256, 256>>>();
    k_inv<<<(NN + 255) / 256, 256>>>();
    k_scatter<<<(NE / 2 * 32 + 255) / 256, 256>>>();   // 16 lanes per edge
    k_max<<<2048, 256>>>(bias);
    k_quant<<<6250, 256>>>(bias, out);
}